// round 15
// baseline (speedup 1.0000x reference)
#include <cuda_runtime.h>
#include <cuda_bf16.h>
#include <math_constants.h>

// Shapes fixed by the dataset instance:
//   xyz:        [B,3,N] float32   B=4, N=16384
//   sparse_xyz: [B,3,M] float32   M=4096
//   sparse_flow:[B,3,M] float32
//   resol_factor: int32 scalar, K: int32 scalar (5)
//   out:        [B,3,N] float32
#define BDIM 4
#define NDIM 16384
#define MDIM 4096
#define TPB  448                    // 14 warps; grid (37,4)=148 CTAs == #SMs (one wave)
#define CTAS_X 37                   // ceil(16384/448)

typedef unsigned long long u64;

// ---- packed f32x2 helpers (Blackwell sm_103a; FFMA2/FADD2/FMUL2 in SASS) ----
__device__ __forceinline__ u64 pk2(float lo, float hi) {
    u64 r; asm("mov.b64 %0, {%1, %2};" : "=l"(r) : "f"(lo), "f"(hi)); return r;
}
__device__ __forceinline__ void upk2(u64 v, float& lo, float& hi) {
    asm("mov.b64 {%0, %1}, %2;" : "=f"(lo), "=f"(hi) : "l"(v));
}
__device__ __forceinline__ u64 add2(u64 a, u64 b) {
    u64 r; asm("add.rn.f32x2 %0, %1, %2;" : "=l"(r) : "l"(a), "l"(b)); return r;
}
__device__ __forceinline__ u64 mul2(u64 a, u64 b) {
    u64 r; asm("mul.rn.f32x2 %0, %1, %2;" : "=l"(r) : "l"(a), "l"(b)); return r;
}
__device__ __forceinline__ u64 fma2(u64 a, u64 b, u64 c) {
    u64 r; asm("fma.rn.f32x2 %0, %1, %2, %3;" : "=l"(r) : "l"(a), "l"(b), "l"(c)); return r;
}

#define INS5(s, j, D0, D1, D2, D3, D4, I0, I1, I2, I3, I4)                             \
    if ((s) < D4) {                                                                    \
        D4 = (s); I4 = (j);                                                            \
        if (D4 < D3) { float t = D3; D3 = D4; D4 = t; int ti = I3; I3 = I4; I4 = ti; } \
        if (D3 < D2) { float t = D2; D2 = D3; D3 = t; int ti = I2; I2 = I3; I3 = ti; } \
        if (D2 < D1) { float t = D1; D1 = D2; D2 = t; int ti = I1; I1 = I2; I2 = ti; } \
        if (D1 < D0) { float t = D0; D0 = D1; D1 = t; int ti = I0; I0 = I1; I1 = ti; } \
    }

__global__ __launch_bounds__(TPB, 1) void upsample_flow(
    const float* __restrict__ xyz,
    const float* __restrict__ sxyz,
    const float* __restrict__ sflow,
    const int* __restrict__ resol_ptr,
    const int* __restrict__ K_ptr,
    float* __restrict__ out)
{
    __shared__ __align__(16) float sx[MDIM];
    __shared__ __align__(16) float sy[MDIM];
    __shared__ __align__(16) float sz[MDIM];

    const int b   = blockIdx.y;
    const int tid = threadIdx.x;
    const int n   = blockIdx.x * TPB + tid;

    const int sbase = b * 3 * MDIM;
    #pragma unroll
    for (int i = tid; i < MDIM; i += TPB) {
        sx[i] = sxyz[sbase + i];
        sy[i] = sxyz[sbase + MDIM + i];
        sz[i] = sxyz[sbase + 2 * MDIM + i];
    }
    __syncthreads();

    if (n >= NDIM) return;   // only the last CTA per batch is underloaded

    const int qbase = b * 3 * NDIM;
    const float qx = xyz[qbase + n];
    const float qy = xyz[qbase + NDIM + n];
    const float qz = xyz[qbase + 2 * NDIM + n];

    const int   K      = *K_ptr;
    const float sigma  = (float)(*resol_ptr);   // INITIAL_RADIUS = 1.0
    const float inv_s2 = 1.0f / (sigma * sigma);

    if (K == 5) {
        // packed (-q, -q): dx = px + (-qx) == px - qx exactly
        const u64 nqx2 = pk2(-qx, -qx);
        const u64 nqy2 = pk2(-qy, -qy);
        const u64 nqz2 = pk2(-qz, -qz);

        float d0 = CUDART_INF_F, d1 = CUDART_INF_F, d2 = CUDART_INF_F,
              d3 = CUDART_INF_F, d4 = CUDART_INF_F;
        int   i0 = 0, i1 = 0, i2 = 0, i3 = 0, i4 = 0;

        const ulonglong2* X2 = (const ulonglong2*)sx;  // each elem = 4 floats
        const ulonglong2* Y2 = (const ulonglong2*)sy;
        const ulonglong2* Z2 = (const ulonglong2*)sz;

        // unroll 8: 8 independent LDS.128x3 + distance chains in flight per thread
        #pragma unroll 8
        for (int g = 0; g < MDIM / 4; ++g) {
            const ulonglong2 xv = X2[g];   // LDS.128 (broadcast)
            const ulonglong2 yv = Y2[g];
            const ulonglong2 zv = Z2[g];

            const u64 dx01 = add2(xv.x, nqx2);
            const u64 dx23 = add2(xv.y, nqx2);
            const u64 dy01 = add2(yv.x, nqy2);
            const u64 dy23 = add2(yv.y, nqy2);
            const u64 dz01 = add2(zv.x, nqz2);
            const u64 dz23 = add2(zv.y, nqz2);

            u64 s01 = mul2(dx01, dx01);
            s01 = fma2(dy01, dy01, s01);
            s01 = fma2(dz01, dz01, s01);
            u64 s23 = mul2(dx23, dx23);
            s23 = fma2(dy23, dy23, s23);
            s23 = fma2(dz23, dz23, s23);

            float s0, s1, s2, s3;
            upk2(s01, s0, s1);
            upk2(s23, s2, s3);

            const float m = fminf(fminf(s0, s1), fminf(s2, s3));
            if (m < d4) {
                const int jb = 4 * g;
                INS5(s0, jb,     d0, d1, d2, d3, d4, i0, i1, i2, i3, i4);
                INS5(s1, jb + 1, d0, d1, d2, d3, d4, i0, i1, i2, i3, i4);
                INS5(s2, jb + 2, d0, d1, d2, d3, d4, i0, i1, i2, i3, i4);
                INS5(s3, jb + 3, d0, d1, d2, d3, d4, i0, i1, i2, i3, i4);
            }
        }

        const float e0 = sqrtf(fmaxf(d0 * inv_s2, 1e-12f));
        const float e1 = sqrtf(fmaxf(d1 * inv_s2, 1e-12f));
        const float e2 = sqrtf(fmaxf(d2 * inv_s2, 1e-12f));
        const float e3 = sqrtf(fmaxf(d3 * inv_s2, 1e-12f));
        const float e4 = sqrtf(fmaxf(d4 * inv_s2, 1e-12f));
        const float em = e0;  // sorted ascending

        const float w0 = __expf(em - e0);
        const float w1 = __expf(em - e1);
        const float w2 = __expf(em - e2);
        const float w3 = __expf(em - e3);
        const float w4 = __expf(em - e4);
        const float inv_w = 1.0f / (w0 + w1 + w2 + w3 + w4);

        const float* f0 = sflow + sbase;
        const float* f1 = f0 + MDIM;
        const float* f2 = f1 + MDIM;
        const float fx = w0*f0[i0] + w1*f0[i1] + w2*f0[i2] + w3*f0[i3] + w4*f0[i4];
        const float fy = w0*f1[i0] + w1*f1[i1] + w2*f1[i2] + w3*f1[i3] + w4*f1[i4];
        const float fz = w0*f2[i0] + w1*f2[i1] + w2*f2[i2] + w3*f2[i3] + w4*f2[i4];

        out[qbase + n]            = fx * inv_w;
        out[qbase + NDIM + n]     = fy * inv_w;
        out[qbase + 2 * NDIM + n] = fz * inv_w;
    } else {
        // ---- generic fallback, K <= 32 (exact; correctness only) ----
        const int KK = (K < 32) ? K : 32;
        float dl[32];
        int   il[32];
        for (int k = 0; k < KK; ++k) { dl[k] = CUDART_INF_F; il[k] = 0; }
        for (int j = 0; j < MDIM; ++j) {
            const float dx = sx[j] - qx;
            const float dy = sy[j] - qy;
            const float dz = sz[j] - qz;
            const float sq = fmaf(dx, dx, fmaf(dy, dy, dz * dz));
            if (sq < dl[KK - 1]) {
                int k = KK - 1;
                while (k > 0 && dl[k - 1] > sq) {
                    dl[k] = dl[k - 1]; il[k] = il[k - 1]; --k;
                }
                dl[k] = sq; il[k] = j;
            }
        }
        const float em = sqrtf(fmaxf(dl[0] * inv_s2, 1e-12f));
        float fx = 0.f, fy = 0.f, fz = 0.f, wsum = 0.f;
        for (int k = 0; k < KK; ++k) {
            const float e = sqrtf(fmaxf(dl[k] * inv_s2, 1e-12f));
            const float w = __expf(em - e);
            wsum += w;
            const int idx = il[k];
            fx += w * sflow[sbase + idx];
            fy += w * sflow[sbase + MDIM + idx];
            fz += w * sflow[sbase + 2 * MDIM + idx];
        }
        const float inv_w = 1.0f / wsum;
        out[qbase + n]            = fx * inv_w;
        out[qbase + NDIM + n]     = fy * inv_w;
        out[qbase + 2 * NDIM + n] = fz * inv_w;
    }
}

extern "C" void kernel_launch(void* const* d_in, const int* in_sizes, int n_in,
                              void* d_out, int out_size)
{
    const float* xyz   = (const float*)d_in[0];
    const float* sxyz  = (const float*)d_in[1];
    const float* sflow = (const float*)d_in[2];
    const int*   resol = (const int*)d_in[3];
    const int*   Kp    = (const int*)d_in[4];
    float* out = (float*)d_out;

    dim3 grid(CTAS_X, BDIM);   // 37 x 4 = 148 CTAs == one CTA per SM, single wave
    upsample_flow<<<grid, TPB>>>(xyz, sxyz, sflow, resol, Kp, out);
}

// round 16
// speedup vs baseline: 1.0417x; 1.0417x over previous
#include <cuda_runtime.h>
#include <cuda_bf16.h>
#include <math_constants.h>

// Shapes fixed by the dataset instance:
//   xyz:        [B,3,N] float32   B=4, N=16384
//   sparse_xyz: [B,3,M] float32   M=4096
//   sparse_flow:[B,3,M] float32
//   resol_factor: int32 scalar, K: int32 scalar (5)
//   out:        [B,3,N] float32
#define BDIM 4
#define NDIM 16384
#define MDIM 4096
#define TPB  448                    // grid (37,4)=148 CTAs == #SMs, one wave
#define CTAS_X 37

// uniform grid for exact KNN
#define NC    32
#define NC3   (NC * NC * NC)
#define GLO   (-4.8f)
#define GH    (0.3f)
#define GINVH (1.0f / GH)

// CSR point storage (built per launch by build_grid; read by upsample_flow)
__device__ float4 g_pts[BDIM][MDIM];        // (x,y,z, orig_idx as float bits), cell-sorted
__device__ int    g_cs [BDIM][NC3 + 1];     // exclusive cell starts

__device__ __forceinline__ int cell_coord(float v) {
    int c = (int)floorf((v - GLO) * GINVH);
    c = c < 0 ? 0 : c;
    c = c > NC - 1 ? NC - 1 : c;
    return c;
}

#define INS5(s, j, D0, D1, D2, D3, D4, I0, I1, I2, I3, I4)                             \
    {                                                                                  \
        D4 = (s); I4 = (j);                                                            \
        if (D4 < D3) { float t = D3; D3 = D4; D4 = t; int ti = I3; I3 = I4; I4 = ti; } \
        if (D3 < D2) { float t = D2; D2 = D3; D3 = t; int ti = I2; I2 = I3; I3 = ti; } \
        if (D2 < D1) { float t = D1; D1 = D2; D2 = t; int ti = I1; I1 = I2; I2 = ti; } \
        if (D1 < D0) { float t = D0; D0 = D1; D1 = t; int ti = I0; I0 = I1; I1 = ti; } \
    }

// ---------------- Kernel 1: build CSR grid (one CTA per batch) ---------------
__global__ __launch_bounds__(512) void build_grid(const float* __restrict__ sxyz)
{
    extern __shared__ int hist[];   // NC3 ints (dynamic, 128 KB)
    __shared__ int wsum[16];

    const int b = blockIdx.x;
    const int t = threadIdx.x;
    const int sbase = b * 3 * MDIM;

    for (int i = t; i < NC3; i += 512) hist[i] = 0;
    __syncthreads();

    // histogram
    for (int i = t; i < MDIM; i += 512) {
        const float x = sxyz[sbase + i];
        const float y = sxyz[sbase + MDIM + i];
        const float z = sxyz[sbase + 2 * MDIM + i];
        const int ci = (cell_coord(z) * NC + cell_coord(y)) * NC + cell_coord(x);
        atomicAdd(&hist[ci], 1);
    }
    __syncthreads();

    // per-thread chunk sums (64 cells each), then block exclusive scan
    const int base = t * 64;
    int csum = 0;
    #pragma unroll
    for (int k = 0; k < 64; ++k) csum += hist[base + k];

    const int lane = t & 31, wid = t >> 5;
    int v = csum;
    #pragma unroll
    for (int o = 1; o < 32; o <<= 1) {
        int u = __shfl_up_sync(0xFFFFFFFFu, v, o);
        if (lane >= o) v += u;
    }
    if (lane == 31) wsum[wid] = v;
    __syncthreads();
    if (wid == 0) {
        int s = (lane < 16) ? wsum[lane] : 0;
        #pragma unroll
        for (int o = 1; o < 16; o <<= 1) {
            int u = __shfl_up_sync(0xFFFFFFFFu, s, o);
            if (lane >= o) s += u;
        }
        if (lane < 16) wsum[lane] = s;
    }
    __syncthreads();
    const int warp_off = (wid == 0) ? 0 : wsum[wid - 1];
    int run = warp_off + v - csum;   // exclusive prefix for this chunk

    // write exclusive starts (into hist in-place + global)
    #pragma unroll
    for (int k = 0; k < 64; ++k) {
        const int c = hist[base + k];
        hist[base + k] = run;
        g_cs[b][base + k] = run;
        run += c;
    }
    if (t == 511) g_cs[b][NC3] = MDIM;
    __syncthreads();

    // scatter (hist now holds cursors)
    for (int i = t; i < MDIM; i += 512) {
        const float x = sxyz[sbase + i];
        const float y = sxyz[sbase + MDIM + i];
        const float z = sxyz[sbase + 2 * MDIM + i];
        const int ci = (cell_coord(z) * NC + cell_coord(y)) * NC + cell_coord(x);
        const int pos = atomicAdd(&hist[ci], 1);
        g_pts[b][pos] = make_float4(x, y, z, __int_as_float(i));
    }
}

// ---------------- Kernel 2: ring-search KNN + softmax flow --------------------
// dynamic smem: float4 spts[MDIM]  (64 KB)  then  int scs[NC3+1]  (128 KB)
#define SMEM2 (MDIM * (int)sizeof(float4) + (NC3 + 1) * (int)sizeof(int))

__global__ __launch_bounds__(TPB, 1) void upsample_flow(
    const float* __restrict__ xyz,
    const float* __restrict__ sflow,
    const int* __restrict__ resol_ptr,
    const int* __restrict__ K_ptr,
    float* __restrict__ out)
{
    extern __shared__ __align__(16) char smem_raw[];
    float4* spts = (float4*)smem_raw;
    int*    scs  = (int*)(smem_raw + MDIM * sizeof(float4));

    const int b   = blockIdx.y;
    const int tid = threadIdx.x;
    const int n   = blockIdx.x * TPB + tid;

    for (int i = tid; i < MDIM; i += TPB)  spts[i] = g_pts[b][i];
    for (int i = tid; i <= NC3; i += TPB)  scs[i]  = g_cs[b][i];
    __syncthreads();

    if (n >= NDIM) return;

    const int qbase = b * 3 * NDIM;
    const float qx = xyz[qbase + n];
    const float qy = xyz[qbase + NDIM + n];
    const float qz = xyz[qbase + 2 * NDIM + n];

    const int   K      = *K_ptr;
    const float sigma  = (float)(*resol_ptr);   // INITIAL_RADIUS = 1.0
    const float inv_s2 = 1.0f / (sigma * sigma);
    const int   sbase  = b * 3 * MDIM;

    if (K == 5) {
        float d0 = CUDART_INF_F, d1 = CUDART_INF_F, d2 = CUDART_INF_F,
              d3 = CUDART_INF_F, d4 = CUDART_INF_F;
        int   i0 = 0, i1 = 0, i2 = 0, i3 = 0, i4 = 0;

        const int cx = cell_coord(qx);
        const int cy = cell_coord(qy);
        const int cz = cell_coord(qz);

        #define SCAN_RANGE(BEG, END)                                                   \
            for (int t2 = (BEG); t2 < (END); ++t2) {                                   \
                const float4 p = spts[t2];                                             \
                const float dx = p.x - qx, dy = p.y - qy, dz = p.z - qz;               \
                const float sq = fmaf(dx, dx, fmaf(dy, dy, dz * dz));                  \
                if (sq < d4) {                                                         \
                    const int jj = __float_as_int(p.w);                                \
                    INS5(sq, jj, d0, d1, d2, d3, d4, i0, i1, i2, i3, i4);              \
                }                                                                      \
            }

        for (int r = 0; r <= NC; ++r) {
            const int z0 = max(cz - r, 0), z1 = min(cz + r, NC - 1);
            const int y0 = max(cy - r, 0), y1 = min(cy + r, NC - 1);
            const int x0 = max(cx - r, 0), x1 = min(cx + r, NC - 1);

            for (int zz = z0; zz <= z1; ++zz) {
                const bool ze = (zz == cz - r) || (zz == cz + r);
                for (int yy = y0; yy <= y1; ++yy) {
                    const bool ye = (yy == cy - r) || (yy == cy + r);
                    const int rb = (zz * NC + yy) * NC;
                    if (ze || ye) {
                        // whole row is at Chebyshev distance r: contiguous range
                        const int beg = scs[rb + x0];
                        const int end = scs[rb + x1 + 1];
                        SCAN_RANGE(beg, end)
                    } else {
                        const int xl = cx - r, xr = cx + r;
                        if (xl >= 0) {
                            const int beg = scs[rb + xl];
                            const int end = scs[rb + xl + 1];
                            SCAN_RANGE(beg, end)
                        }
                        if (xr <= NC - 1) {
                            const int beg = scs[rb + xr];
                            const int end = scs[rb + xr + 1];
                            SCAN_RANGE(beg, end)
                        }
                    }
                }
            }

            // termination: d5 <= distance to nearest uncovered region.
            // grid-edge sides count as covered (points there are clamped INTO
            // edge cells, so "beyond edge cell" holds no points).
            float bnd = CUDART_INF_F;
            if (cx - r > 0)      bnd = fminf(bnd, qx - (GLO + (cx - r) * GH));
            if (cx + r < NC - 1) bnd = fminf(bnd, (GLO + (cx + r + 1) * GH) - qx);
            if (cy - r > 0)      bnd = fminf(bnd, qy - (GLO + (cy - r) * GH));
            if (cy + r < NC - 1) bnd = fminf(bnd, (GLO + (cy + r + 1) * GH) - qy);
            if (cz - r > 0)      bnd = fminf(bnd, qz - (GLO + (cz - r) * GH));
            if (cz + r < NC - 1) bnd = fminf(bnd, (GLO + (cz + r + 1) * GH) - qz);
            if (d4 <= bnd * bnd) break;
        }
        #undef SCAN_RANGE

        const float e0 = sqrtf(fmaxf(d0 * inv_s2, 1e-12f));
        const float e1 = sqrtf(fmaxf(d1 * inv_s2, 1e-12f));
        const float e2 = sqrtf(fmaxf(d2 * inv_s2, 1e-12f));
        const float e3 = sqrtf(fmaxf(d3 * inv_s2, 1e-12f));
        const float e4 = sqrtf(fmaxf(d4 * inv_s2, 1e-12f));
        const float em = e0;  // sorted ascending

        const float w0 = __expf(em - e0);
        const float w1 = __expf(em - e1);
        const float w2 = __expf(em - e2);
        const float w3 = __expf(em - e3);
        const float w4 = __expf(em - e4);
        const float inv_w = 1.0f / (w0 + w1 + w2 + w3 + w4);

        const float* f0 = sflow + sbase;
        const float* f1 = f0 + MDIM;
        const float* f2 = f1 + MDIM;
        const float fx = w0*f0[i0] + w1*f0[i1] + w2*f0[i2] + w3*f0[i3] + w4*f0[i4];
        const float fy = w0*f1[i0] + w1*f1[i1] + w2*f1[i2] + w3*f1[i3] + w4*f1[i4];
        const float fz = w0*f2[i0] + w1*f2[i1] + w2*f2[i2] + w3*f2[i3] + w4*f2[i4];

        out[qbase + n]            = fx * inv_w;
        out[qbase + NDIM + n]     = fy * inv_w;
        out[qbase + 2 * NDIM + n] = fz * inv_w;
    } else {
        // ---- generic fallback, K <= 32: linear scan of cell-sorted points ----
        const int KK = (K < 32) ? K : 32;
        float dl[32];
        int   il[32];
        for (int k = 0; k < KK; ++k) { dl[k] = CUDART_INF_F; il[k] = 0; }
        for (int j = 0; j < MDIM; ++j) {
            const float4 p = spts[j];
            const float dx = p.x - qx, dy = p.y - qy, dz = p.z - qz;
            const float sq = fmaf(dx, dx, fmaf(dy, dy, dz * dz));
            if (sq < dl[KK - 1]) {
                int k = KK - 1;
                while (k > 0 && dl[k - 1] > sq) {
                    dl[k] = dl[k - 1]; il[k] = il[k - 1]; --k;
                }
                dl[k] = sq; il[k] = __float_as_int(p.w);
            }
        }
        const float em = sqrtf(fmaxf(dl[0] * inv_s2, 1e-12f));
        float fx = 0.f, fy = 0.f, fz = 0.f, wsum2 = 0.f;
        for (int k = 0; k < KK; ++k) {
            const float e = sqrtf(fmaxf(dl[k] * inv_s2, 1e-12f));
            const float w = __expf(em - e);
            wsum2 += w;
            const int idx = il[k];
            fx += w * sflow[sbase + idx];
            fy += w * sflow[sbase + MDIM + idx];
            fz += w * sflow[sbase + 2 * MDIM + idx];
        }
        const float inv_w = 1.0f / wsum2;
        out[qbase + n]            = fx * inv_w;
        out[qbase + NDIM + n]     = fy * inv_w;
        out[qbase + 2 * NDIM + n] = fz * inv_w;
    }
}

extern "C" void kernel_launch(void* const* d_in, const int* in_sizes, int n_in,
                              void* d_out, int out_size)
{
    const float* xyz   = (const float*)d_in[0];
    const float* sxyz  = (const float*)d_in[1];
    const float* sflow = (const float*)d_in[2];
    const int*   resol = (const int*)d_in[3];
    const int*   Kp    = (const int*)d_in[4];
    float* out = (float*)d_out;

    // large dynamic smem opt-ins (idempotent host attributes; capture-safe)
    cudaFuncSetAttribute(build_grid,
                         cudaFuncAttributeMaxDynamicSharedMemorySize, NC3 * 4);
    cudaFuncSetAttribute(upsample_flow,
                         cudaFuncAttributeMaxDynamicSharedMemorySize, SMEM2);

    build_grid<<<BDIM, 512, NC3 * 4>>>(sxyz);

    dim3 grid(CTAS_X, BDIM);   // 148 CTAs == one per SM, single wave
    upsample_flow<<<grid, TPB, SMEM2>>>(xyz, sflow, resol, Kp, out);
}